// round 6
// baseline (speedup 1.0000x reference)
#include <cuda_runtime.h>
#include <math.h>

#define Hh 256
#define Ww 512
#define CELLS (Hh*Ww)        /* 131072 */
#define NPER (CELLS*2)       /* 262144 */
#define NTOT (NPER*2)        /* 524288 */
#define KTOP 4096
#define CAP 16384
#define SCORE_THR 0.2f
#define NMS_THR 0.15f

/* spatial bins for sparse IoU */
#define GX 24
#define GY 12
#define NBINS (GX*GY)
#define BCAP 256
#define BININV (1.0f/12.0f)
#define X0 (-144.0f)
#define Y0 (-72.0f)

__device__ unsigned int g_hist[65536];
__device__ unsigned int g_cnt;
__device__ unsigned int g_T;
__device__ float g_scores[NTOT];
__device__ unsigned long long g_keys[CAP];
__device__ unsigned long long g_topkeys[KTOP];
__device__ float4 g_sb[KTOP];
__device__ float g_topsc[KTOP];
__device__ unsigned long long g_mask[KTOP*64];
__device__ int g_bin_cnt[NBINS];
__device__ int g_bin_items[NBINS*BCAP];

__device__ __forceinline__ unsigned int f2ord(float f){
    unsigned int u = __float_as_uint(f);
    return (u & 0x80000000u) ? ~u : (u | 0x80000000u);
}
__device__ __forceinline__ float ord2f(unsigned int o){
    unsigned int u = (o & 0x80000000u) ? (o & 0x7fffffffu) : ~o;
    return __uint_as_float(u);
}

/* zero hist, counters, mask, bin counters.  grid 1024x256 = 262144 threads */
__global__ void zero_k(){
    int i = blockIdx.x*blockDim.x + threadIdx.x;
    g_mask[i] = 0ull;                     /* 262144 words */
    if (i < 65536) g_hist[i] = 0;
    if (i < NBINS) g_bin_cnt[i] = 0;
    if (i == 0) g_cnt = 0;
}

__global__ void score_k(const float* __restrict__ psm_v, const float* __restrict__ psm_i){
    int g = blockIdx.x*blockDim.x + threadIdx.x;
    if (g >= NTOT) return;
    int br = g >= NPER ? 1 : 0;
    int p = g - br*NPER;
    int a = p & 1;
    int cell = p >> 1;
    const float* psm = br ? psm_i : psm_v;
    float x = psm[a*CELLS + cell];
    float s = 1.0f / (1.0f + expf(-x));
    float m = (s > SCORE_THR) ? s : -1.0f;
    g_scores[g] = m;
    bool below = !(s > SCORE_THR);
    unsigned int bal = __ballot_sync(0xffffffffu, below);
    if (below){
        if ((threadIdx.x & 31) == (unsigned)(__ffs(bal) - 1))
            atomicAdd(&g_hist[0xBF80u], __popc(bal));
    } else {
        unsigned int hp = (~f2ord(m)) >> 16;
        atomicAdd(&g_hist[hp], 1u);
    }
}

__global__ void select_k(){
    __shared__ unsigned int coarse[256];
    __shared__ unsigned int fine[256];
    __shared__ int s_Tc;
    __shared__ unsigned int s_cum;
    int t = threadIdx.x;
    unsigned int s = 0;
    #pragma unroll 8
    for (int i = 0; i < 256; i++) s += g_hist[t*256 + i];
    coarse[t] = s;
    __syncthreads();
    if (t == 0){
        unsigned int cum = 0, cumb = 0; int Tc = 255;
        int found = 0;
        #pragma unroll
        for (int c = 0; c < 256; c++){
            unsigned int nc = cum + coarse[c];
            if (!found && nc >= KTOP){ Tc = c; cumb = cum; found = 1; }
            cum = nc;
        }
        s_Tc = Tc; s_cum = cumb;
    }
    __syncthreads();
    fine[t] = g_hist[s_Tc*256 + t];
    __syncthreads();
    if (t == 0){
        unsigned int cum = s_cum; int Tp = s_Tc*256 + 255;
        int found = 0;
        #pragma unroll
        for (int f = 0; f < 256; f++){
            unsigned int nc = cum + fine[f];
            if (!found && nc >= KTOP){ Tp = s_Tc*256 + f; found = 1; }
            cum = nc;
        }
        g_T = (unsigned int)Tp;
    }
}

__global__ void gather_k(){
    int g = blockIdx.x*blockDim.x + threadIdx.x;
    if (g >= NTOT) return;
    float m = g_scores[g];
    unsigned int ko = ~f2ord(m);
    if ((ko >> 16) <= g_T){
        unsigned int pos = atomicAdd(&g_cnt, 1u);
        if (pos < CAP)
            g_keys[pos] = ((unsigned long long)ko << 32) | (unsigned int)g;
    }
}

/* exact ordering by rank-counting: position of key i == #{ j : key_j < key_i } */
__global__ void rank_k(){
    __shared__ unsigned long long tile[256];
    unsigned int M = g_cnt; if (M > CAP) M = CAP;
    if (blockIdx.x*256 >= (int)M) return;   /* uniform early exit */
    int i = blockIdx.x*256 + threadIdx.x;
    unsigned long long my = (i < (int)M) ? g_keys[i] : 0xFFFFFFFFFFFFFFFFULL;
    int cnt = 0;
    int ntiles = ((int)M + 255) >> 8;
    for (int tb = 0; tb < ntiles; tb++){
        int j = tb*256 + threadIdx.x;
        tile[threadIdx.x] = (j < (int)M) ? g_keys[j] : 0xFFFFFFFFFFFFFFFFULL;
        __syncthreads();
        #pragma unroll 16
        for (int c = 0; c < 256; c++)
            cnt += (tile[c] < my) ? 1 : 0;
        __syncthreads();
    }
    if (i < (int)M && cnt < KTOP) g_topkeys[cnt] = my;
}

__device__ __forceinline__ void make_corners(float bx,float by,float bz,float bh,float bw,float bl,float yaw,
                                             float* cx,float* cy,float* cz){
    const float sx[8]={0.5f,0.5f,-0.5f,-0.5f,0.5f,0.5f,-0.5f,-0.5f};
    const float sy[8]={0.5f,-0.5f,-0.5f,0.5f,0.5f,-0.5f,-0.5f,0.5f};
    const float sz[8]={-0.5f,-0.5f,-0.5f,-0.5f,0.5f,0.5f,0.5f,0.5f};
    float c = cosf(yaw), s = sinf(yaw);
    #pragma unroll
    for (int k = 0; k < 8; k++){
        float x = bl*sx[k], y = bw*sy[k], z = bh*sz[k];
        cx[k] = x*c - y*s + bx;
        cy[k] = x*s + y*c + by;
        cz[k] = z + bz;
    }
}

__device__ __forceinline__ void xform(const float* __restrict__ T, float* cx,float* cy,float* cz){
    float r00=T[0],r01=T[1],r02=T[2],tx=T[3];
    float r10=T[4],r11=T[5],r12=T[6],ty=T[7];
    float r20=T[8],r21=T[9],r22=T[10],tz=T[11];
    #pragma unroll
    for (int k = 0; k < 8; k++){
        float x=cx[k], y=cy[k], z=cz[k];
        cx[k] = r00*x + r01*y + r02*z + tx;
        cy[k] = r10*x + r11*y + r12*z + ty;
        cz[k] = r20*x + r21*y + r22*z + tz;
    }
}

__global__ void boxes_k(const float* __restrict__ anchors,
                        const float* __restrict__ rm_v, const float* __restrict__ rm_i,
                        const float* __restrict__ t_proj, const float* __restrict__ t_ego,
                        float* __restrict__ out){
    int r = blockIdx.x*blockDim.x + threadIdx.x;
    if (r >= KTOP) return;
    unsigned long long key = g_topkeys[r];
    unsigned int idx = (unsigned int)(key & 0xFFFFFFFFu);
    unsigned int ko  = (unsigned int)(key >> 32);
    float score = ord2f(~ko);
    g_topsc[r] = score;

    int br = (idx >= (unsigned)NPER) ? 1 : 0;
    int p = (int)idx - br*NPER;
    int a = p & 1;
    int cell = p >> 1;
    const float* rm = br ? rm_i : rm_v;
    const float* anc = anchors + (size_t)p * 7;

    float d0 = rm[(a*7+0)*CELLS + cell];
    float d1 = rm[(a*7+1)*CELLS + cell];
    float d2 = rm[(a*7+2)*CELLS + cell];
    float d3 = rm[(a*7+3)*CELLS + cell];
    float d4 = rm[(a*7+4)*CELLS + cell];
    float d5 = rm[(a*7+5)*CELLS + cell];
    float d6 = rm[(a*7+6)*CELLS + cell];

    float a0=anc[0], a1=anc[1], a2=anc[2], a3=anc[3], a4=anc[4], a5=anc[5], a6=anc[6];
    float ad = sqrtf(a4*a4 + a5*a5);
    float bx = d0*ad + a0;
    float by = d1*ad + a1;
    float bz = d2*a3 + a2;
    float bh = expf(d3)*a3;
    float bw = expf(d4)*a4;
    float bl = expf(d5)*a5;
    float byaw = d6 + a6;

    float cx[8], cy[8], cz[8];
    make_corners(bx,by,bz,bh,bw,bl,byaw,cx,cy,cz);

    if (br){
        xform(t_proj, cx, cy, cz);
        float mx=0,my=0,mz=0;
        #pragma unroll
        for (int k=0;k<8;k++){ mx+=cx[k]; my+=cy[k]; mz+=cz[k]; }
        mx *= 0.125f; my *= 0.125f; mz *= 0.125f;
        float nh = (cz[4]+cz[5]+cz[6]+cz[7])*0.25f - (cz[0]+cz[1]+cz[2]+cz[3])*0.25f;
        const int la[4]={0,1,4,5}, lb[4]={3,2,7,6};
        const int wa[4]={0,3,4,7}, wb[4]={1,2,5,6};
        float ll=0.0f, wwv=0.0f, dsx=0.0f, dsy=0.0f;
        #pragma unroll
        for (int m=0;m<4;m++){
            float dx = cx[la[m]]-cx[lb[m]], dy = cy[la[m]]-cy[lb[m]];
            ll += sqrtf(dx*dx + dy*dy);
            dsx += dx; dsy += dy;
            float ex = cx[wa[m]]-cx[wb[m]], ey = cy[wa[m]]-cy[wb[m]];
            wwv += sqrtf(ex*ex + ey*ey);
        }
        ll *= 0.25f; wwv *= 0.25f;
        float nyaw = atan2f(dsy, dsx);
        make_corners(mx,my,mz,nh,wwv,ll,nyaw,cx,cy,cz);
    }

    xform(t_ego, cx, cy, cz);

    float mnx = cx[0], mny = cy[0], mxx = cx[0], mxy = cy[0];
    #pragma unroll
    for (int k = 0; k < 8; k++){
        out[(size_t)r*25 + k*3 + 0] = cx[k];
        out[(size_t)r*25 + k*3 + 1] = cy[k];
        out[(size_t)r*25 + k*3 + 2] = cz[k];
        mnx = fminf(mnx, cx[k]); mny = fminf(mny, cy[k]);
        mxx = fmaxf(mxx, cx[k]); mxy = fmaxf(mxy, cy[k]);
    }
    g_sb[r] = make_float4(mnx, mny, mxx, mxy);

    /* fused bin insert (uses registers just computed) */
    float bcx = 0.5f*(mnx + mxx);
    float bcy = 0.5f*(mny + mxy);
    int bbx = (int)floorf((bcx - X0)*BININV);
    int bby = (int)floorf((bcy - Y0)*BININV);
    bbx = min(max(bbx, 0), GX-1);
    bby = min(max(bby, 0), GY-1);
    int bin = bby*GX + bbx;
    int pos = atomicAdd(&g_bin_cnt[bin], 1);
    if (pos < BCAP) g_bin_items[bin*BCAP + pos] = r;
}

/* sparse IoU: each thread owns one box, scans 3x3 neighborhood bins */
__global__ void pairs_k(){
    int r = blockIdx.x*blockDim.x + threadIdx.x;
    if (r >= KTOP) return;
    float4 rb = g_sb[r];
    float cxm = 0.5f*(rb.x + rb.z);
    float cym = 0.5f*(rb.y + rb.w);
    int bx0 = (int)floorf((cxm - X0)*BININV);
    int by0 = (int)floorf((cym - Y0)*BININV);
    bx0 = min(max(bx0, 0), GX-1);
    by0 = min(max(by0, 0), GY-1);
    float ar = (rb.z - rb.x)*(rb.w - rb.y);
    for (int dy = -1; dy <= 1; dy++){
        int by = by0 + dy;
        if (by < 0 || by >= GY) continue;
        for (int dx = -1; dx <= 1; dx++){
            int bx = bx0 + dx;
            if (bx < 0 || bx >= GX) continue;
            int bin = by*GX + bx;
            int n = g_bin_cnt[bin];
            if (n > BCAP) n = BCAP;
            const int* items = &g_bin_items[bin*BCAP];
            for (int q = 0; q < n; q++){
                int c = items[q];
                if (c <= r) continue;     /* only col > row bits */
                float4 b = g_sb[c];
                float ltx = fmaxf(rb.x, b.x), lty = fmaxf(rb.y, b.y);
                float rbx = fminf(rb.z, b.z), rby = fminf(rb.w, b.w);
                float iw = fmaxf(rbx-ltx, 0.0f), ih = fmaxf(rby-lty, 0.0f);
                float inter = iw*ih;
                if (inter > 0.0f){
                    float ac = (b.z-b.x)*(b.w-b.y);
                    float iou = inter / (ar + ac - inter + 1e-6f);
                    if (iou > NMS_THR)
                        atomicOr(&g_mask[(size_t)r*64 + (c >> 6)], 1ull << (c & 63));
                }
            }
        }
    }
}

__global__ void reduce_k(float* __restrict__ out){
    __shared__ unsigned long long diag[64][64];   /* 32 KB: diag[b][j] = mask[b*64+j][word b] */
    __shared__ unsigned long long remv[64];
    __shared__ unsigned long long kept[64];
    __shared__ unsigned int validh[128];
    int tid = threadIdx.x;   /* 1024 threads */
    for (int i = tid; i < 4096; i += 1024){
        int b = i >> 6, jj = i & 63;
        diag[b][jj] = g_mask[(size_t)i*64 + b];
    }
    #pragma unroll
    for (int p = 0; p < 4; p++){
        int i = p*1024 + tid;
        bool v = g_topsc[i] > SCORE_THR;
        unsigned int bal = __ballot_sync(0xffffffffu, v);
        if ((tid & 31) == 0) validh[i >> 5] = bal;
    }
    if (tid < 64) remv[tid] = 0ull;
    __syncthreads();

    int j = tid >> 4;        /* 0..63 : row within block */
    int c = tid & 15;        /* 0..15 : word-chunk */
    for (int b = 0; b < 64; b++){
        if (tid == 0){
            unsigned long long r = remv[b], k = 0ull;
            unsigned long long val = ((unsigned long long)validh[b*2+1] << 32) | validh[b*2];
            #pragma unroll
            for (int jj = 0; jj < 64; jj++){
                unsigned long long lm = diag[b][jj];
                bool take = (((val >> jj) & 1ull) != 0ull) && (((r >> jj) & 1ull) == 0ull);
                if (take){ k |= (1ull << jj); r |= lm; }
            }
            kept[b] = k;
        }
        __syncthreads();
        unsigned long long k = kept[b];
        if ((k >> j) & 1ull){
            const unsigned long long* row = &g_mask[(size_t)(b*64 + j)*64];
            #pragma unroll
            for (int w = 0; w < 4; w++){
                unsigned long long m = row[c*4 + w];
                if (m) atomicOr(&remv[c*4 + w], m);
            }
        }
        __syncthreads();
    }
    for (int i = tid; i < KTOP; i += 1024){
        float keep = ((kept[i >> 6] >> (i & 63)) & 1ull) ? 1.0f : 0.0f;
        out[(size_t)i*25 + 24] = g_topsc[i] * keep;
    }
}

extern "C" void kernel_launch(void* const* d_in, const int* in_sizes, int n_in,
                              void* d_out, int out_size){
    const float* anchors = (const float*)d_in[0];
    const float* psm_v   = (const float*)d_in[1];
    const float* rm_v    = (const float*)d_in[2];
    const float* psm_i   = (const float*)d_in[3];
    const float* rm_i    = (const float*)d_in[4];
    const float* t_proj  = (const float*)d_in[5];
    const float* t_ego   = (const float*)d_in[6];
    float* out = (float*)d_out;

    zero_k<<<1024, 256>>>();
    score_k<<<NTOT/256, 256>>>(psm_v, psm_i);
    select_k<<<1, 256>>>();
    gather_k<<<NTOT/256, 256>>>();
    rank_k<<<CAP/256, 256>>>();
    boxes_k<<<KTOP/128, 128>>>(anchors, rm_v, rm_i, t_proj, t_ego, out);
    pairs_k<<<KTOP/256, 256>>>();
    reduce_k<<<1, 1024>>>(out);
}

// round 7
// speedup vs baseline: 2.0756x; 2.0756x over previous
#include <cuda_runtime.h>
#include <math.h>

#define Hh 256
#define Ww 512
#define CELLS (Hh*Ww)        /* 131072 */
#define NPER (CELLS*2)       /* 262144 */
#define NTOT (NPER*2)        /* 524288 */
#define KTOP 4096
#define CAP 8192
#define SCORE_THR 0.2f
#define NMS_THR 0.15f

/* spatial bins for sparse IoU */
#define GX 24
#define GY 12
#define NBINS (GX*GY)
#define BCAP 256
#define BININV (1.0f/12.0f)
#define X0 (-144.0f)
#define Y0 (-72.0f)

__device__ unsigned int g_chist[4096];    /* 12-bit prefix histogram */
__device__ unsigned int g_fhist[256];     /* fine 8-bit within winning bin */
__device__ unsigned int g_cnt;
__device__ unsigned int g_T12;            /* winning 12-bit prefix */
__device__ unsigned int g_C12;            /* count strictly before it */
__device__ unsigned int g_T;              /* 20-bit threshold prefix */
__device__ unsigned int g_ko[NTOT];       /* descending-order ordinal per element */
__device__ unsigned long long g_keys[CAP];
__device__ unsigned long long g_topkeys[KTOP];
__device__ float4 g_sb[KTOP];
__device__ float g_topsc[KTOP];
__device__ unsigned long long g_mask[KTOP*64];
__device__ int g_bin_cnt[NBINS];
__device__ int g_bin_items[NBINS*BCAP];

__device__ __forceinline__ unsigned int f2ord(float f){
    unsigned int u = __float_as_uint(f);
    return (u & 0x80000000u) ? ~u : (u | 0x80000000u);
}
__device__ __forceinline__ float ord2f(unsigned int o){
    unsigned int u = (o & 0x80000000u) ? (o & 0x7fffffffu) : ~o;
    return __uint_as_float(u);
}

/* grid-stride clear: mask (262144 w), chist, fhist, bin counters. 1024x256 */
__global__ void zero_k(){
    int i = blockIdx.x*blockDim.x + threadIdx.x;
    g_mask[i] = 0ull;
    if (i < 4096) g_chist[i] = 0;
    if (i < 256)  g_fhist[i] = 0;
    if (i < NBINS) g_bin_cnt[i] = 0;
    if (i == 0) g_cnt = 0;
}

__global__ void score_k(const float* __restrict__ psm_v, const float* __restrict__ psm_i){
    __shared__ unsigned int sh[4096];
    int t = threadIdx.x;
    for (int i = t; i < 4096; i += 256) sh[i] = 0;
    __syncthreads();
    int g = blockIdx.x*256 + t;
    int br = g >= NPER ? 1 : 0;
    int p = g - br*NPER;
    const float* psm = br ? psm_i : psm_v;
    float x = psm[(p & 1)*CELLS + (p >> 1)];
    float s = 1.0f / (1.0f + expf(-x));
    float m = (s > SCORE_THR) ? s : -1.0f;
    unsigned int ko = ~f2ord(m);
    g_ko[g] = ko;
    atomicAdd(&sh[ko >> 20], 1u);
    __syncthreads();
    for (int i = t; i < 4096; i += 256){
        unsigned int v = sh[i];
        if (v) atomicAdd(&g_chist[i], v);
    }
}

/* stage-1 select over 4096 coarse bins (1 block, 256 thr) */
__global__ void sel1_k(){
    __shared__ unsigned int sh[4096];
    __shared__ unsigned int part[256];
    int t = threadIdx.x;
    #pragma unroll
    for (int i = 0; i < 16; i++) sh[i*256 + t] = g_chist[i*256 + t];
    __syncthreads();
    unsigned int p = 0;
    #pragma unroll
    for (int k = 0; k < 16; k++) p += sh[t*16 + k];
    part[t] = p;
    __syncthreads();
    if (t == 0){
        unsigned int cum = 0; int seg = 255;
        for (int sgi = 0; sgi < 256; sgi++){
            if (cum + part[sgi] >= KTOP){ seg = sgi; break; }
            cum += part[sgi];
        }
        unsigned int c = cum; int b = seg*16 + 15;
        for (int k = 0; k < 16; k++){
            unsigned int v = sh[seg*16 + k];
            if (c + v >= KTOP){ b = seg*16 + k; break; }
            c += v;
        }
        g_T12 = (unsigned int)b;
        g_C12 = c;
    }
}

/* fine histogram of bits [12,20) within the winning 12-bit bin */
__global__ void fine_k(){
    int g = blockIdx.x*blockDim.x + threadIdx.x;
    unsigned int ko = g_ko[g];
    if ((ko >> 20) == g_T12)
        atomicAdd(&g_fhist[(ko >> 12) & 0xFFu], 1u);
}

__global__ void sel2_k(){
    __shared__ unsigned int sh[256];
    int t = threadIdx.x;
    sh[t] = g_fhist[t];
    __syncthreads();
    if (t == 0){
        unsigned int cum = g_C12, T12 = g_T12;
        int f = 255;
        for (int i = 0; i < 256; i++){
            if (cum + sh[i] >= KTOP){ f = i; break; }
            cum += sh[i];
        }
        g_T = (T12 << 8) | (unsigned int)f;
    }
}

/* gather candidates (20-bit prefix <= threshold), warp-aggregated counter */
__global__ void gather_k(){
    int g = blockIdx.x*blockDim.x + threadIdx.x;
    unsigned int ko = g_ko[g];
    bool cond = (ko >> 12) <= g_T;
    unsigned int bal = __ballot_sync(0xffffffffu, cond);
    if (cond){
        int lane = threadIdx.x & 31;
        int leader = __ffs(bal) - 1;
        unsigned int base;
        if (lane == leader) base = atomicAdd(&g_cnt, (unsigned int)__popc(bal));
        base = __shfl_sync(0xffffffffu, base, leader);
        unsigned int pos = base + __popc(bal & ((1u << lane) - 1u));
        if (pos < CAP)
            g_keys[pos] = ((unsigned long long)ko << 32) | (unsigned int)g;
    }
}

/* exact ordering by rank-counting */
__global__ void rank_k(){
    __shared__ unsigned long long tile[256];
    unsigned int M = g_cnt; if (M > CAP) M = CAP;
    if (blockIdx.x*256 >= (int)M) return;
    int i = blockIdx.x*256 + threadIdx.x;
    unsigned long long my = (i < (int)M) ? g_keys[i] : 0xFFFFFFFFFFFFFFFFULL;
    int cnt = 0;
    int ntiles = ((int)M + 255) >> 8;
    for (int tb = 0; tb < ntiles; tb++){
        int j = tb*256 + threadIdx.x;
        tile[threadIdx.x] = (j < (int)M) ? g_keys[j] : 0xFFFFFFFFFFFFFFFFULL;
        __syncthreads();
        #pragma unroll 16
        for (int c = 0; c < 256; c++)
            cnt += (tile[c] < my) ? 1 : 0;
        __syncthreads();
    }
    if (i < (int)M && cnt < KTOP) g_topkeys[cnt] = my;
}

__device__ __forceinline__ void make_corners(float bx,float by,float bz,float bh,float bw,float bl,float yaw,
                                             float* cx,float* cy,float* cz){
    const float sx[8]={0.5f,0.5f,-0.5f,-0.5f,0.5f,0.5f,-0.5f,-0.5f};
    const float sy[8]={0.5f,-0.5f,-0.5f,0.5f,0.5f,-0.5f,-0.5f,0.5f};
    const float sz[8]={-0.5f,-0.5f,-0.5f,-0.5f,0.5f,0.5f,0.5f,0.5f};
    float c = cosf(yaw), s = sinf(yaw);
    #pragma unroll
    for (int k = 0; k < 8; k++){
        float x = bl*sx[k], y = bw*sy[k], z = bh*sz[k];
        cx[k] = x*c - y*s + bx;
        cy[k] = x*s + y*c + by;
        cz[k] = z + bz;
    }
}

__device__ __forceinline__ void xform(const float* __restrict__ T, float* cx,float* cy,float* cz){
    float r00=T[0],r01=T[1],r02=T[2],tx=T[3];
    float r10=T[4],r11=T[5],r12=T[6],ty=T[7];
    float r20=T[8],r21=T[9],r22=T[10],tz=T[11];
    #pragma unroll
    for (int k = 0; k < 8; k++){
        float x=cx[k], y=cy[k], z=cz[k];
        cx[k] = r00*x + r01*y + r02*z + tx;
        cy[k] = r10*x + r11*y + r12*z + ty;
        cz[k] = r20*x + r21*y + r22*z + tz;
    }
}

__global__ void boxes_k(const float* __restrict__ anchors,
                        const float* __restrict__ rm_v, const float* __restrict__ rm_i,
                        const float* __restrict__ t_proj, const float* __restrict__ t_ego,
                        float* __restrict__ out){
    int r = blockIdx.x*blockDim.x + threadIdx.x;
    if (r >= KTOP) return;
    unsigned long long key = g_topkeys[r];
    unsigned int idx = (unsigned int)(key & 0xFFFFFFFFu);
    unsigned int ko  = (unsigned int)(key >> 32);
    float score = ord2f(~ko);
    g_topsc[r] = score;

    int br = (idx >= (unsigned)NPER) ? 1 : 0;
    int p = (int)idx - br*NPER;
    int a = p & 1;
    int cell = p >> 1;
    const float* rm = br ? rm_i : rm_v;
    const float* anc = anchors + (size_t)p * 7;

    float d0 = rm[(a*7+0)*CELLS + cell];
    float d1 = rm[(a*7+1)*CELLS + cell];
    float d2 = rm[(a*7+2)*CELLS + cell];
    float d3 = rm[(a*7+3)*CELLS + cell];
    float d4 = rm[(a*7+4)*CELLS + cell];
    float d5 = rm[(a*7+5)*CELLS + cell];
    float d6 = rm[(a*7+6)*CELLS + cell];

    float a0=anc[0], a1=anc[1], a2=anc[2], a3=anc[3], a4=anc[4], a5=anc[5], a6=anc[6];
    float ad = sqrtf(a4*a4 + a5*a5);
    float bx = d0*ad + a0;
    float by = d1*ad + a1;
    float bz = d2*a3 + a2;
    float bh = expf(d3)*a3;
    float bw = expf(d4)*a4;
    float bl = expf(d5)*a5;
    float byaw = d6 + a6;

    float cx[8], cy[8], cz[8];
    make_corners(bx,by,bz,bh,bw,bl,byaw,cx,cy,cz);

    if (br){
        xform(t_proj, cx, cy, cz);
        float mx=0,my=0,mz=0;
        #pragma unroll
        for (int k=0;k<8;k++){ mx+=cx[k]; my+=cy[k]; mz+=cz[k]; }
        mx *= 0.125f; my *= 0.125f; mz *= 0.125f;
        float nh = (cz[4]+cz[5]+cz[6]+cz[7])*0.25f - (cz[0]+cz[1]+cz[2]+cz[3])*0.25f;
        const int la[4]={0,1,4,5}, lb[4]={3,2,7,6};
        const int wa[4]={0,3,4,7}, wb[4]={1,2,5,6};
        float ll=0.0f, wwv=0.0f, dsx=0.0f, dsy=0.0f;
        #pragma unroll
        for (int m=0;m<4;m++){
            float dx = cx[la[m]]-cx[lb[m]], dy = cy[la[m]]-cy[lb[m]];
            ll += sqrtf(dx*dx + dy*dy);
            dsx += dx; dsy += dy;
            float ex = cx[wa[m]]-cx[wb[m]], ey = cy[wa[m]]-cy[wb[m]];
            wwv += sqrtf(ex*ex + ey*ey);
        }
        ll *= 0.25f; wwv *= 0.25f;
        float nyaw = atan2f(dsy, dsx);
        make_corners(mx,my,mz,nh,wwv,ll,nyaw,cx,cy,cz);
    }

    xform(t_ego, cx, cy, cz);

    float mnx = cx[0], mny = cy[0], mxx = cx[0], mxy = cy[0];
    #pragma unroll
    for (int k = 0; k < 8; k++){
        out[(size_t)r*25 + k*3 + 0] = cx[k];
        out[(size_t)r*25 + k*3 + 1] = cy[k];
        out[(size_t)r*25 + k*3 + 2] = cz[k];
        mnx = fminf(mnx, cx[k]); mny = fminf(mny, cy[k]);
        mxx = fmaxf(mxx, cx[k]); mxy = fmaxf(mxy, cy[k]);
    }
    g_sb[r] = make_float4(mnx, mny, mxx, mxy);

    /* fused bin insert */
    float bcx = 0.5f*(mnx + mxx);
    float bcy = 0.5f*(mny + mxy);
    int bbx = (int)floorf((bcx - X0)*BININV);
    int bby = (int)floorf((bcy - Y0)*BININV);
    bbx = min(max(bbx, 0), GX-1);
    bby = min(max(bby, 0), GY-1);
    int bin = bby*GX + bbx;
    int pos = atomicAdd(&g_bin_cnt[bin], 1);
    if (pos < BCAP) g_bin_items[bin*BCAP + pos] = r;
}

/* sparse IoU via 3x3 bin neighborhood */
__global__ void pairs_k(){
    int r = blockIdx.x*blockDim.x + threadIdx.x;
    if (r >= KTOP) return;
    float4 rb = g_sb[r];
    float cxm = 0.5f*(rb.x + rb.z);
    float cym = 0.5f*(rb.y + rb.w);
    int bx0 = (int)floorf((cxm - X0)*BININV);
    int by0 = (int)floorf((cym - Y0)*BININV);
    bx0 = min(max(bx0, 0), GX-1);
    by0 = min(max(by0, 0), GY-1);
    float ar = (rb.z - rb.x)*(rb.w - rb.y);
    for (int dy = -1; dy <= 1; dy++){
        int by = by0 + dy;
        if (by < 0 || by >= GY) continue;
        for (int dx = -1; dx <= 1; dx++){
            int bx = bx0 + dx;
            if (bx < 0 || bx >= GX) continue;
            int bin = by*GX + bx;
            int n = g_bin_cnt[bin];
            if (n > BCAP) n = BCAP;
            const int* items = &g_bin_items[bin*BCAP];
            for (int q = 0; q < n; q++){
                int c = items[q];
                if (c <= r) continue;
                float4 b = g_sb[c];
                float ltx = fmaxf(rb.x, b.x), lty = fmaxf(rb.y, b.y);
                float rbx = fminf(rb.z, b.z), rby = fminf(rb.w, b.w);
                float iw = fmaxf(rbx-ltx, 0.0f), ih = fmaxf(rby-lty, 0.0f);
                float inter = iw*ih;
                if (inter > 0.0f){
                    float ac = (b.z-b.x)*(b.w-b.y);
                    float iou = inter / (ar + ac - inter + 1e-6f);
                    if (iou > NMS_THR)
                        atomicOr(&g_mask[(size_t)r*64 + (c >> 6)], 1ull << (c & 63));
                }
            }
        }
    }
}

__global__ void reduce_k(float* __restrict__ out){
    __shared__ unsigned long long diag[64][64];
    __shared__ unsigned long long remv[64];
    __shared__ unsigned long long kept[64];
    __shared__ unsigned int validh[128];
    int tid = threadIdx.x;   /* 1024 threads */
    for (int i = tid; i < 4096; i += 1024){
        int b = i >> 6, jj = i & 63;
        diag[b][jj] = g_mask[(size_t)i*64 + b];
    }
    #pragma unroll
    for (int p = 0; p < 4; p++){
        int i = p*1024 + tid;
        bool v = g_topsc[i] > SCORE_THR;
        unsigned int bal = __ballot_sync(0xffffffffu, v);
        if ((tid & 31) == 0) validh[i >> 5] = bal;
    }
    if (tid < 64) remv[tid] = 0ull;
    __syncthreads();

    int j = tid >> 4;
    int c = tid & 15;
    for (int b = 0; b < 64; b++){
        if (tid == 0){
            unsigned long long r = remv[b], k = 0ull;
            unsigned long long val = ((unsigned long long)validh[b*2+1] << 32) | validh[b*2];
            #pragma unroll
            for (int jj = 0; jj < 64; jj++){
                unsigned long long lm = diag[b][jj];
                bool take = (((val >> jj) & 1ull) != 0ull) && (((r >> jj) & 1ull) == 0ull);
                if (take){ k |= (1ull << jj); r |= lm; }
            }
            kept[b] = k;
        }
        __syncthreads();
        unsigned long long k = kept[b];
        if ((k >> j) & 1ull){
            const unsigned long long* row = &g_mask[(size_t)(b*64 + j)*64];
            #pragma unroll
            for (int w = 0; w < 4; w++){
                unsigned long long m = row[c*4 + w];
                if (m) atomicOr(&remv[c*4 + w], m);
            }
        }
        __syncthreads();
    }
    for (int i = tid; i < KTOP; i += 1024){
        float keep = ((kept[i >> 6] >> (i & 63)) & 1ull) ? 1.0f : 0.0f;
        out[(size_t)i*25 + 24] = g_topsc[i] * keep;
    }
}

extern "C" void kernel_launch(void* const* d_in, const int* in_sizes, int n_in,
                              void* d_out, int out_size){
    const float* anchors = (const float*)d_in[0];
    const float* psm_v   = (const float*)d_in[1];
    const float* rm_v    = (const float*)d_in[2];
    const float* psm_i   = (const float*)d_in[3];
    const float* rm_i    = (const float*)d_in[4];
    const float* t_proj  = (const float*)d_in[5];
    const float* t_ego   = (const float*)d_in[6];
    float* out = (float*)d_out;

    zero_k<<<1024, 256>>>();
    score_k<<<NTOT/256, 256>>>(psm_v, psm_i);
    sel1_k<<<1, 256>>>();
    fine_k<<<NTOT/256, 256>>>();
    sel2_k<<<1, 256>>>();
    gather_k<<<NTOT/256, 256>>>();
    rank_k<<<CAP/256, 256>>>();
    boxes_k<<<KTOP/128, 128>>>(anchors, rm_v, rm_i, t_proj, t_ego, out);
    pairs_k<<<KTOP/256, 256>>>();
    reduce_k<<<1, 1024>>>(out);
}